// round 1
// baseline (speedup 1.0000x reference)
#include <cuda_runtime.h>
#include <cstdint>

#define NN 50000
#define NE 800000
#define NBATCH 8
#define HD 128
#define NBLK 391
#define NP (NBLK*128)   // 50048 padded rows

typedef unsigned long long ull;

// ---------------- device scratch (static, no allocations) ----------------
__device__ float  g_h[NP*HD];
__device__ float  g_P[NP*2*HD];
__device__ float  g_agg[NP*HD];
__device__ float  g_Wc[128*256];
__device__ int    g_cnt[NN];
__device__ int    g_fill[NN];
__device__ int    g_rowptr[NN+1];
__device__ int    g_srcs[NE];
__device__ float4 g_ea[NE];
__device__ float  g_invdeg[NN];
__device__ float  g_w[NN];
__device__ float  g_gsum[NBATCH*HD];
__device__ float  g_gcnt[NBATCH];
__device__ float  g_bcsum[NBATCH*HD];
__device__ float  g_bccnt[NBATCH];
__device__ float  g_xg[NBATCH*HD];
__device__ float  g_xbc[NBATCH*HD];
__device__ float  g_gb[NBATCH*HD];
__device__ float  g_S[HD];
__device__ float  g_sw;

// ---------------- f32x2 packed math (Blackwell dual fp32 pipe) ----------------
__device__ __forceinline__ ull pk2(float lo, float hi){
    ull r; asm("mov.b64 %0, {%1,%2};" : "=l"(r) : "f"(lo), "f"(hi)); return r;
}
__device__ __forceinline__ ull fma2(ull a, ull b, ull c){
    ull d; asm("fma.rn.f32x2 %0, %1, %2, %3;" : "=l"(d) : "l"(a), "l"(b), "l"(c)); return d;
}
__device__ __forceinline__ float2 unpk2(ull v){
    float lo, hi; asm("mov.b64 {%0,%1}, %2;" : "=f"(lo), "=f"(hi) : "l"(v));
    float2 f; f.x = lo; f.y = hi; return f;
}

// ---------------- setup kernels ----------------
__global__ void k_zero(){
    int i = blockIdx.x*blockDim.x + threadIdx.x;
    if (i < NN){ g_cnt[i] = 0; g_fill[i] = 0; }
    if (i < NBATCH*HD){ g_gsum[i] = 0.f; g_bcsum[i] = 0.f; }
    if (i < NBATCH){ g_gcnt[i] = 0.f; g_bccnt[i] = 0.f; }
    if (i < HD) g_S[i] = 0.f;
    if (i == 0) g_sw = 0.f;
}

// pack [W1 | W2] (rows 0..127 and 128..255 of W_msg) into K-major 128x256
__global__ void k_packW(const float* __restrict__ Wm){
    int i = blockIdx.x*blockDim.x + threadIdx.x;
    if (i >= 128*256) return;
    int k = i >> 8, j = i & 255;
    g_Wc[i] = (j < 128) ? Wm[k*128 + j] : Wm[(128+k)*128 + (j-128)];
}

// h0 = relu([x|x_mask] @ W_enc + b_enc)
__global__ void k_encode(const float* __restrict__ x, const float* __restrict__ xm,
                         const float* __restrict__ We, const float* __restrict__ be){
    int node = blockIdx.x*2 + (threadIdx.x >> 7);
    int t = threadIdx.x & 127;
    if (node >= NN) return;
    const float* xr = x  + node*5;
    const float* mr = xm + node*3;
    float acc = be[t];
    acc += xr[0]*We[0*128+t];
    acc += xr[1]*We[1*128+t];
    acc += xr[2]*We[2*128+t];
    acc += xr[3]*We[3*128+t];
    acc += xr[4]*We[4*128+t];
    acc += mr[0]*We[5*128+t];
    acc += mr[1]*We[6*128+t];
    acc += mr[2]*We[7*128+t];
    g_h[node*HD + t] = fmaxf(acc, 0.f);
}

// w_i = (1/64) * sum_j cos((pos_i - sp) . M_j)   (exact closed form of nk_i . nq)
__global__ void k_wcoef(const float* __restrict__ pos, const float* __restrict__ M,
                        const float* __restrict__ sp){
    int i = blockIdx.x*blockDim.x + threadIdx.x;
    if (i >= NN) return;
    float d0 = pos[i*2]   - sp[0];
    float d1 = pos[i*2+1] - sp[1];
    float sum = 0.f;
    #pragma unroll 8
    for (int j = 0; j < 64; j++)
        sum += cosf(d0*M[j] + d1*M[64+j]);
    g_w[i] = sum * (1.f/64.f);
}

__global__ void k_count(const int* __restrict__ ei){
    int e = blockIdx.x*blockDim.x + threadIdx.x;
    if (e < NE) atomicAdd(&g_cnt[ei[NE + e]], 1);
}

// single-block exclusive scan of degree counts -> rowptr; also invdeg
__global__ void k_scan(){
    __shared__ int sh[1024];
    __shared__ int s_carry;
    int tid = threadIdx.x;
    if (tid == 0) s_carry = 0;
    __syncthreads();
    for (int base = 0; base < NN; base += 1024){
        int n = base + tid;
        int v = (n < NN) ? g_cnt[n] : 0;
        if (n < NN) g_invdeg[n] = 1.f / (float)max(v, 1);
        sh[tid] = v;
        __syncthreads();
        for (int off = 1; off < 1024; off <<= 1){
            int add = (tid >= off) ? sh[tid - off] : 0;
            __syncthreads();
            sh[tid] += add;
            __syncthreads();
        }
        int incl  = sh[tid];
        int total = sh[1023];
        int carry = s_carry;
        if (n < NN) g_rowptr[n] = carry + incl - v;
        __syncthreads();
        if (tid == 0) s_carry = carry + total;
    }
    __syncthreads();
    if (tid == 0) g_rowptr[NN] = s_carry;
}

__global__ void k_scatter(const int* __restrict__ ei, const float* __restrict__ ea){
    int e = blockIdx.x*blockDim.x + threadIdx.x;
    if (e >= NE) return;
    int s = ei[e];
    int d = ei[NE + e];
    int p = g_rowptr[d] + atomicAdd(&g_fill[d], 1);
    g_srcs[p] = s;
    const float* a = ea + e*3;
    g_ea[p] = make_float4(a[0], a[1], a[2], 0.f);
}

// initial segment sums: graph mean of h and bc-weighted mean (batch sorted)
__global__ void k_seginit(const int* __restrict__ batch, const float* __restrict__ xm){
    const int nchunk = (NN + gridDim.x - 1) / gridDim.x;
    int n0 = blockIdx.x * nchunk;
    int n1 = min(n0 + nchunk, NN);
    int t = threadIdx.x;
    if (n0 >= n1) return;
    int cur = batch[n0];
    float aG = 0.f, aB = 0.f, cG = 0.f, cB = 0.f;
    for (int n = n0; n < n1; n++){
        int b = batch[n];
        if (b != cur){
            atomicAdd(&g_gsum[cur*HD+t], aG);
            atomicAdd(&g_bcsum[cur*HD+t], aB);
            if (t == 0){ atomicAdd(&g_gcnt[cur], cG); atomicAdd(&g_bccnt[cur], cB); }
            aG = aB = cG = cB = 0.f; cur = b;
        }
        float hv = g_h[n*HD + t];
        float bc = xm[n*3 + 2];
        aG += hv; aB += hv*bc;
        if (t == 0){ cG += 1.f; cB += bc; }
    }
    atomicAdd(&g_gsum[cur*HD+t], aG);
    atomicAdd(&g_bcsum[cur*HD+t], aB);
    if (t == 0){ atomicAdd(&g_gcnt[cur], cG); atomicAdd(&g_bccnt[cur], cB); }
}

__global__ void k_divinit(){
    int i = threadIdx.x;                 // 1024 threads = 8*128
    int g = i >> 7;
    g_xg[i]  = g_gsum[i]  / fmaxf(g_gcnt[g], 1.f);
    g_xbc[i] = g_bcsum[i] / fmaxf(g_bccnt[g], 1.f);
}

__global__ void k_segzero(){
    int i = threadIdx.x;
    g_gsum[i] = 0.f;
    if (i < NBATCH) g_gcnt[i] = 0.f;
}

__global__ void k_segsum(const int* __restrict__ batch){
    const int nchunk = (NN + gridDim.x - 1) / gridDim.x;
    int n0 = blockIdx.x * nchunk;
    int n1 = min(n0 + nchunk, NN);
    int t = threadIdx.x;
    if (n0 >= n1) return;
    int cur = batch[n0];
    float aG = 0.f, cG = 0.f;
    for (int n = n0; n < n1; n++){
        int b = batch[n];
        if (b != cur){
            atomicAdd(&g_gsum[cur*HD+t], aG);
            if (t == 0) atomicAdd(&g_gcnt[cur], cG);
            aG = 0.f; cG = 0.f; cur = b;
        }
        aG += g_h[n*HD + t];
        if (t == 0) cG += 1.f;
    }
    atomicAdd(&g_gsum[cur*HD+t], aG);
    if (t == 0) atomicAdd(&g_gcnt[cur], cG);
}

__global__ void k_segdiv(){
    int i = threadIdx.x;
    int g = i >> 7;
    g_xg[i] = g_gsum[i] / fmaxf(g_gcnt[g], 1.f);
}

// per-graph bias: gb = xg@W_upd[256:384] + xbc@W_upd[384:512] + b_upd
__global__ void k_gb(const float* __restrict__ Wu, const float* __restrict__ bu){
    int g = blockIdx.x, t = threadIdx.x;
    float acc = bu[t];
    #pragma unroll 4
    for (int k = 0; k < 128; k++) acc += g_xg[g*HD+k]  * Wu[(256+k)*128 + t];
    #pragma unroll 4
    for (int k = 0; k < 128; k++) acc += g_xbc[g*HD+k] * Wu[(384+k)*128 + t];
    g_gb[g*HD + t] = acc;
}

// ---------------- GEMM1: P[NP,256] = h[NP,128] @ Wc[128,256] (f32x2) ----------------
__global__ void __launch_bounds__(256, 2) k_gemm1(){
    __shared__ float As[16][132];
    __shared__ float Bs[16][128];
    int tid  = threadIdx.x;
    int row0 = blockIdx.x * 128;
    int col0 = blockIdx.y * 128;
    int ty = tid >> 4, tx = tid & 15;
    ull acc[8][4];
    #pragma unroll
    for (int r = 0; r < 8; r++)
        #pragma unroll
        for (int c = 0; c < 4; c++) acc[r][c] = 0ull;

    for (int k0 = 0; k0 < 128; k0 += 16){
        #pragma unroll
        for (int i = 0; i < 2; i++){
            int idx = tid*2 + i;
            int r = idx >> 2, kq = (idx & 3) << 2;
            float4 v = *(const float4*)&g_h[(row0 + r)*HD + k0 + kq];
            As[kq+0][r] = v.x; As[kq+1][r] = v.y; As[kq+2][r] = v.z; As[kq+3][r] = v.w;
        }
        #pragma unroll
        for (int i = 0; i < 2; i++){
            int idx = tid*2 + i;
            int r = idx >> 5, c = (idx & 31) << 2;
            *(float4*)&Bs[r][c] = *(const float4*)&g_Wc[(k0 + r)*256 + col0 + c];
        }
        __syncthreads();
        #pragma unroll
        for (int kk = 0; kk < 16; kk++){
            ull av[8], bv[4];
            #pragma unroll
            for (int r = 0; r < 8; r++){ float a = As[kk][ty*8 + r]; av[r] = pk2(a, a); }
            #pragma unroll
            for (int c = 0; c < 4; c++){
                float2 b = *(const float2*)&Bs[kk][tx*8 + c*2];
                bv[c] = pk2(b.x, b.y);
            }
            #pragma unroll
            for (int r = 0; r < 8; r++)
                #pragma unroll
                for (int c = 0; c < 4; c++) acc[r][c] = fma2(av[r], bv[c], acc[r][c]);
        }
        __syncthreads();
    }
    #pragma unroll
    for (int r = 0; r < 8; r++){
        int row = row0 + ty*8 + r;
        #pragma unroll
        for (int c = 0; c < 4; c++){
            float2 v = unpk2(acc[r][c]);
            *(float2*)&g_P[row*256 + col0 + tx*8 + c*2] = v;
        }
    }
}

// ---------------- edge aggregation over CSR (no atomics) ----------------
__global__ void k_agg(const float* __restrict__ Wm, const float* __restrict__ bm){
    int n = blockIdx.x;
    int t = threadIdx.x;
    float base = g_P[n*256 + 128 + t] + bm[t];
    float w0 = Wm[256*128 + t], w1 = Wm[257*128 + t], w2 = Wm[258*128 + t];
    int s0 = g_rowptr[n], s1 = g_rowptr[n+1];
    float acc = 0.f;
    int k = s0;
    for (; k + 1 < s1; k += 2){
        int sA = g_srcs[k], sB = g_srcs[k+1];
        float4 eA = g_ea[k], eB = g_ea[k+1];
        float pA = g_P[sA*256 + t];
        float pB = g_P[sB*256 + t];
        acc += fmaxf(pA + base + eA.x*w0 + eA.y*w1 + eA.z*w2, 0.f);
        acc += fmaxf(pB + base + eB.x*w0 + eB.y*w1 + eB.z*w2, 0.f);
    }
    if (k < s1){
        int s = g_srcs[k];
        float4 e = g_ea[k];
        acc += fmaxf(g_P[s*256 + t] + base + e.x*w0 + e.y*w1 + e.z*w2, 0.f);
    }
    g_agg[n*HD + t] = acc * g_invdeg[n];
}

// ---------------- GEMM2: h += relu([h|agg] @ W_upd[0:256] + gb[batch]) ----------------
__global__ void __launch_bounds__(256, 2) k_gemm2(const float* __restrict__ Wu,
                                                  const int* __restrict__ batch){
    __shared__ float As[16][132];
    __shared__ float Bs[16][128];
    int tid  = threadIdx.x;
    int row0 = blockIdx.x * 128;
    int ty = tid >> 4, tx = tid & 15;
    ull acc[8][4];
    #pragma unroll
    for (int r = 0; r < 8; r++)
        #pragma unroll
        for (int c = 0; c < 4; c++) acc[r][c] = 0ull;

    for (int k0 = 0; k0 < 256; k0 += 16){
        const float* Asrc = (k0 < 128) ? g_h : g_agg;
        int kb = k0 & 127;
        #pragma unroll
        for (int i = 0; i < 2; i++){
            int idx = tid*2 + i;
            int r = idx >> 2, kq = (idx & 3) << 2;
            float4 v = *(const float4*)&Asrc[(row0 + r)*HD + kb + kq];
            As[kq+0][r] = v.x; As[kq+1][r] = v.y; As[kq+2][r] = v.z; As[kq+3][r] = v.w;
        }
        #pragma unroll
        for (int i = 0; i < 2; i++){
            int idx = tid*2 + i;
            int r = idx >> 5, c = (idx & 31) << 2;
            *(float4*)&Bs[r][c] = *(const float4*)&Wu[(k0 + r)*128 + c];
        }
        __syncthreads();
        #pragma unroll
        for (int kk = 0; kk < 16; kk++){
            ull av[8], bv[4];
            #pragma unroll
            for (int r = 0; r < 8; r++){ float a = As[kk][ty*8 + r]; av[r] = pk2(a, a); }
            #pragma unroll
            for (int c = 0; c < 4; c++){
                float2 b = *(const float2*)&Bs[kk][tx*8 + c*2];
                bv[c] = pk2(b.x, b.y);
            }
            #pragma unroll
            for (int r = 0; r < 8; r++)
                #pragma unroll
                for (int c = 0; c < 4; c++) acc[r][c] = fma2(av[r], bv[c], acc[r][c]);
        }
        __syncthreads();
    }
    #pragma unroll
    for (int r = 0; r < 8; r++){
        int row = row0 + ty*8 + r;
        if (row < NN){
            int b = batch[row];
            #pragma unroll
            for (int c = 0; c < 4; c++){
                int col = tx*8 + c*2;
                float2 v  = unpk2(acc[r][c]);
                float2 gb = *(const float2*)&g_gb[b*HD + col];
                float2 hv = *(const float2*)&g_h[row*HD + col];
                float2 o;
                o.x = hv.x + fmaxf(v.x + gb.x, 0.f);
                o.y = hv.y + fmaxf(v.y + gb.y, 0.f);
                *(float2*)&g_h[row*HD + col] = o;
            }
        } else {
            #pragma unroll
            for (int c = 0; c < 4; c++)
                *(float2*)&g_h[row*HD + tx*8 + c*2] = make_float2(0.f, 0.f);
        }
    }
}

// ---------------- decode + weighted global sums ----------------
__global__ void k_decode(const float* __restrict__ Wd, const float* __restrict__ bd,
                         float* __restrict__ out){
    __shared__ float sred[4][4];
    int t = threadIdx.x;
    int lane = t & 31, wp = t >> 5;
    int n0 = blockIdx.x * 32;
    int nmax = min(n0 + 32, NN);
    float w0 = Wd[t*4], w1 = Wd[t*4+1], w2 = Wd[t*4+2], w3 = Wd[t*4+3];
    float Sacc = 0.f, wacc = 0.f;
    for (int n = n0; n < nmax; n++){
        float hv = g_h[n*HD + t];
        float wn = g_w[n];
        Sacc += (1.f + wn) * hv;
        if (t == 0) wacc += wn;
        float p0 = hv*w0, p1 = hv*w1, p2 = hv*w2, p3 = hv*w3;
        #pragma unroll
        for (int off = 16; off > 0; off >>= 1){
            p0 += __shfl_down_sync(0xffffffffu, p0, off);
            p1 += __shfl_down_sync(0xffffffffu, p1, off);
            p2 += __shfl_down_sync(0xffffffffu, p2, off);
            p3 += __shfl_down_sync(0xffffffffu, p3, off);
        }
        if (lane == 0){ sred[wp][0]=p0; sred[wp][1]=p1; sred[wp][2]=p2; sred[wp][3]=p3; }
        __syncthreads();
        if (t < 4)
            out[(1+n)*4 + t] = sred[0][t] + sred[1][t] + sred[2][t] + sred[3][t] + bd[t];
        __syncthreads();
    }
    atomicAdd(&g_S[t], Sacc);
    if (t == 0) atomicAdd(&g_sw, wacc);
}

__global__ void k_final(const float* __restrict__ Wd, const float* __restrict__ bd,
                        float* __restrict__ out){
    __shared__ float sred[4][4];
    int t = threadIdx.x;
    int lane = t & 31, wp = t >> 5;
    float enc = g_S[t] / ((float)NN + g_sw);
    float p0 = enc*Wd[t*4], p1 = enc*Wd[t*4+1], p2 = enc*Wd[t*4+2], p3 = enc*Wd[t*4+3];
    #pragma unroll
    for (int off = 16; off > 0; off >>= 1){
        p0 += __shfl_down_sync(0xffffffffu, p0, off);
        p1 += __shfl_down_sync(0xffffffffu, p1, off);
        p2 += __shfl_down_sync(0xffffffffu, p2, off);
        p3 += __shfl_down_sync(0xffffffffu, p3, off);
    }
    if (lane == 0){ sred[wp][0]=p0; sred[wp][1]=p1; sred[wp][2]=p2; sred[wp][3]=p3; }
    __syncthreads();
    if (t < 4)
        out[t] = sred[0][t] + sred[1][t] + sred[2][t] + sred[3][t] + bd[t];
}

// ---------------- launch ----------------
extern "C" void kernel_launch(void* const* d_in, const int* in_sizes, int n_in,
                              void* d_out, int out_size){
    (void)in_sizes; (void)n_in; (void)out_size;
    const float* x   = (const float*)d_in[0];
    const float* xm  = (const float*)d_in[1];
    const int*   ei  = (const int*)  d_in[2];
    const float* ea  = (const float*)d_in[3];
    const float* pos = (const float*)d_in[4];
    const int*   bat = (const int*)  d_in[5];
    const float* sp  = (const float*)d_in[6];
    const float* M   = (const float*)d_in[7];
    const float* We  = (const float*)d_in[8];
    const float* be  = (const float*)d_in[9];
    const float* Wm  = (const float*)d_in[10];
    const float* bm  = (const float*)d_in[11];
    const float* Wu  = (const float*)d_in[12];
    const float* bu  = (const float*)d_in[13];
    const float* Wd  = (const float*)d_in[14];
    const float* bd  = (const float*)d_in[15];
    float* out = (float*)d_out;

    k_zero   <<<(NN+255)/256, 256>>>();
    k_packW  <<<(128*256+255)/256, 256>>>(Wm);
    k_encode <<<(NN+1)/2, 256>>>(x, xm, We, be);
    k_wcoef  <<<(NN+255)/256, 256>>>(pos, M, sp);
    k_count  <<<(NE+255)/256, 256>>>(ei);
    k_scan   <<<1, 1024>>>();
    k_scatter<<<(NE+255)/256, 256>>>(ei, ea);
    k_seginit<<<512, 128>>>(bat, xm);
    k_divinit<<<1, 1024>>>();

    for (int r = 0; r < 4; r++){
        dim3 g1(NBLK, 2);
        k_gemm1<<<g1, 256>>>();
        k_agg  <<<NN, 128>>>(Wm, bm);
        k_gb   <<<NBATCH, 128>>>(Wu, bu);
        k_gemm2<<<NBLK, 256>>>(Wu, bat);
        if (r < 3){
            k_segzero<<<1, 1024>>>();
            k_segsum <<<512, 128>>>(bat);
            k_segdiv <<<1, 1024>>>();
        }
    }

    k_decode<<<(NN+31)/32, 128>>>(Wd, bd, out);
    k_final <<<1, 128>>>(Wd, bd, out);
}

// round 3
// speedup vs baseline: 1.3836x; 1.3836x over previous
#include <cuda_runtime.h>
#include <cuda_bf16.h>
#include <cstdint>

#define NN 50000
#define NE 800000
#define NBATCH 8
#define HD 128
#define NBLK 391
#define NP (NBLK*128)   // 50048 padded rows

// ---------------- device scratch (static, no allocations) ----------------
__device__ float  g_h[NP*HD];
__device__ float  g_P[NP*2*HD];
__device__ float  g_agg[NP*HD];
__device__ int    g_cnt[NN];
__device__ int    g_fill[NN];
__device__ int    g_rowptr[NN+1];
__device__ int    g_srcs[NE];
__device__ float4 g_ea[NE];
__device__ float  g_invdeg[NN];
__device__ float  g_w[NN];
__device__ float  g_gsum[NBATCH*HD];
__device__ float  g_gcnt[NBATCH];
__device__ float  g_bcsum[NBATCH*HD];
__device__ float  g_bccnt[NBATCH];
__device__ float  g_xg[NBATCH*HD];
__device__ float  g_xbc[NBATCH*HD];
__device__ float  g_gb[NBATCH*HD];
__device__ float  g_S[HD];
__device__ float  g_sw;
// pre-split bf16 weights, [N][K] row-major (K contiguous)
__device__ __nv_bfloat16 g_B1hi[256*128];
__device__ __nv_bfloat16 g_B1lo[256*128];
__device__ __nv_bfloat16 g_B2hi[128*256];
__device__ __nv_bfloat16 g_B2lo[128*256];

// ---------------- smem geometry ----------------
#define PITCH 136                     // bf16 elements per row (272B, conflict-free)
#define TILE_ELEMS (128*PITCH)        // 17408 bf16 per tile
#define SM_AHI 0
#define SM_ALO (TILE_ELEMS)
#define SM_BHI (2*TILE_ELEMS)
#define SM_BLO (3*TILE_ELEMS)
#define SM_TOTAL_BYTES (4*TILE_ELEMS*2)   // 139264

// ---------------- mma.sync bf16 m16n8k16 ----------------
__device__ __forceinline__ void mma16816(float* d, const uint32_t* a, const uint32_t* b){
    asm volatile("mma.sync.aligned.m16n8k16.row.col.f32.bf16.bf16.f32 "
        "{%0,%1,%2,%3}, {%4,%5,%6,%7}, {%8,%9}, {%0,%1,%2,%3};"
        : "+f"(d[0]), "+f"(d[1]), "+f"(d[2]), "+f"(d[3])
        : "r"(a[0]), "r"(a[1]), "r"(a[2]), "r"(a[3]), "r"(b[0]), "r"(b[1]));
}

__device__ __forceinline__ uint32_t lds32(const __nv_bfloat16* p){
    return *(const uint32_t*)p;
}

// split a float into bf16 hi + bf16 lo
__device__ __forceinline__ void bsplit(float v, __nv_bfloat16& hi, __nv_bfloat16& lo){
    hi = __float2bfloat16(v);
    lo = __float2bfloat16(v - __bfloat162float(hi));
}

// load 128-row x 128-col float A block -> smem hi/lo tiles (pitch PITCH)
__device__ __forceinline__ void load_A_tile(const float* A, __nv_bfloat16* sAhi,
                                            __nv_bfloat16* sAlo, int tid){
    const float4* A4 = (const float4*)A;
    #pragma unroll
    for (int i = 0; i < 16; i++){
        int f = tid + i*256;
        int r = f >> 5, c4 = f & 31;
        float4 v = A4[f];
        __nv_bfloat16* dh = sAhi + r*PITCH + c4*4;
        __nv_bfloat16* dl = sAlo + r*PITCH + c4*4;
        __nv_bfloat16 h0,l0,h1,l1,h2,l2,h3,l3;
        bsplit(v.x,h0,l0); bsplit(v.y,h1,l1); bsplit(v.z,h2,l2); bsplit(v.w,h3,l3);
        dh[0]=h0; dh[1]=h1; dh[2]=h2; dh[3]=h3;
        dl[0]=l0; dl[1]=l1; dl[2]=l2; dl[3]=l3;
    }
}

// copy 128x128 bf16 block (row stride srcPitch) -> smem (pitch PITCH)
__device__ __forceinline__ void load_B_tile(const __nv_bfloat16* src, int srcPitch,
                                            __nv_bfloat16* dst, int tid){
    #pragma unroll
    for (int i = 0; i < 8; i++){
        int f = tid + i*256;           // 2048 chunks of 8 bf16
        int n = f >> 4, k8 = f & 15;
        *(uint4*)(dst + n*PITCH + k8*8) = *(const uint4*)(src + n*srcPitch + k8*8);
    }
}

// one K=128 compute stage: acc += Ahi*Bhi + Alo*Bhi + Ahi*Blo
__device__ __forceinline__ void mma_stage(const __nv_bfloat16* sm, float acc[2][8][4],
                                          int w, int l){
    int wm = w >> 1, wn = w & 1;
    int g = l >> 2, t2 = (l & 3) * 2;
    #pragma unroll
    for (int ks = 0; ks < 8; ks++){
        int k0 = ks*16;
        uint32_t ah[2][4], al[2][4], bh[8][2], bl[8][2];
        #pragma unroll
        for (int mb = 0; mb < 2; mb++){
            int rb = (wm*32 + mb*16 + g) * PITCH + k0 + t2;
            ah[mb][0] = lds32(sm + SM_AHI + rb);
            ah[mb][1] = lds32(sm + SM_AHI + rb + 8*PITCH);
            ah[mb][2] = lds32(sm + SM_AHI + rb + 8);
            ah[mb][3] = lds32(sm + SM_AHI + rb + 8*PITCH + 8);
            al[mb][0] = lds32(sm + SM_ALO + rb);
            al[mb][1] = lds32(sm + SM_ALO + rb + 8*PITCH);
            al[mb][2] = lds32(sm + SM_ALO + rb + 8);
            al[mb][3] = lds32(sm + SM_ALO + rb + 8*PITCH + 8);
        }
        #pragma unroll
        for (int nb = 0; nb < 8; nb++){
            int nbb = (wn*64 + nb*8 + g) * PITCH + k0 + t2;
            bh[nb][0] = lds32(sm + SM_BHI + nbb);
            bh[nb][1] = lds32(sm + SM_BHI + nbb + 8);
            bl[nb][0] = lds32(sm + SM_BLO + nbb);
            bl[nb][1] = lds32(sm + SM_BLO + nbb + 8);
        }
        #pragma unroll
        for (int mb = 0; mb < 2; mb++)
            #pragma unroll
            for (int nb = 0; nb < 8; nb++){
                mma16816(acc[mb][nb], ah[mb], bh[nb]);
                mma16816(acc[mb][nb], al[mb], bh[nb]);
                mma16816(acc[mb][nb], ah[mb], bl[nb]);
            }
    }
}

// ---------------- setup kernels ----------------
__global__ void k_zero(){
    int i = blockIdx.x*blockDim.x + threadIdx.x;
    if (i < NN){ g_cnt[i] = 0; g_fill[i] = 0; }
    if (i < NBATCH*HD){ g_gsum[i] = 0.f; g_bcsum[i] = 0.f; }
    if (i < NBATCH){ g_gcnt[i] = 0.f; g_bccnt[i] = 0.f; }
    if (i < HD) g_S[i] = 0.f;
    if (i == 0) g_sw = 0.f;
}

// B1[n][k]: n<128 -> Wm[k][n]; n>=128 -> Wm[128+k][n-128]
__global__ void k_packB1(const float* __restrict__ Wm){
    int i = blockIdx.x*blockDim.x + threadIdx.x;
    if (i >= 256*128) return;
    int n = i >> 7, k = i & 127;
    float v = (n < 128) ? Wm[k*128 + n] : Wm[(128+k)*128 + (n-128)];
    __nv_bfloat16 hi, lo; bsplit(v, hi, lo);
    g_B1hi[i] = hi; g_B1lo[i] = lo;
}

// B2[n][k] = Wu[k*128 + n], n<128, k<256
__global__ void k_packB2(const float* __restrict__ Wu){
    int i = blockIdx.x*blockDim.x + threadIdx.x;
    if (i >= 128*256) return;
    int n = i >> 8, k = i & 255;
    float v = Wu[k*128 + n];
    __nv_bfloat16 hi, lo; bsplit(v, hi, lo);
    g_B2hi[i] = hi; g_B2lo[i] = lo;
}

__global__ void k_encode(const float* __restrict__ x, const float* __restrict__ xm,
                         const float* __restrict__ We, const float* __restrict__ be){
    int node = blockIdx.x*2 + (threadIdx.x >> 7);
    int t = threadIdx.x & 127;
    if (node >= NN) return;
    const float* xr = x  + node*5;
    const float* mr = xm + node*3;
    float acc = be[t];
    acc += xr[0]*We[0*128+t];
    acc += xr[1]*We[1*128+t];
    acc += xr[2]*We[2*128+t];
    acc += xr[3]*We[3*128+t];
    acc += xr[4]*We[4*128+t];
    acc += mr[0]*We[5*128+t];
    acc += mr[1]*We[6*128+t];
    acc += mr[2]*We[7*128+t];
    g_h[node*HD + t] = fmaxf(acc, 0.f);
}

__global__ void k_wcoef(const float* __restrict__ pos, const float* __restrict__ M,
                        const float* __restrict__ sp){
    int i = blockIdx.x*blockDim.x + threadIdx.x;
    if (i >= NN) return;
    float d0 = pos[i*2]   - sp[0];
    float d1 = pos[i*2+1] - sp[1];
    float sum = 0.f;
    #pragma unroll 8
    for (int j = 0; j < 64; j++)
        sum += cosf(d0*M[j] + d1*M[64+j]);
    g_w[i] = sum * (1.f/64.f);
}

__global__ void k_count(const int* __restrict__ ei){
    int e = blockIdx.x*blockDim.x + threadIdx.x;
    if (e < NE) atomicAdd(&g_cnt[ei[NE + e]], 1);
}

__global__ void k_scan(){
    __shared__ int sh[1024];
    __shared__ int s_carry;
    int tid = threadIdx.x;
    if (tid == 0) s_carry = 0;
    __syncthreads();
    for (int base = 0; base < NN; base += 1024){
        int n = base + tid;
        int v = (n < NN) ? g_cnt[n] : 0;
        if (n < NN) g_invdeg[n] = 1.f / (float)max(v, 1);
        sh[tid] = v;
        __syncthreads();
        for (int off = 1; off < 1024; off <<= 1){
            int add = (tid >= off) ? sh[tid - off] : 0;
            __syncthreads();
            sh[tid] += add;
            __syncthreads();
        }
        int incl  = sh[tid];
        int total = sh[1023];
        int carry = s_carry;
        if (n < NN) g_rowptr[n] = carry + incl - v;
        __syncthreads();
        if (tid == 0) s_carry = carry + total;
    }
    __syncthreads();
    if (tid == 0) g_rowptr[NN] = s_carry;
}

__global__ void k_scatter(const int* __restrict__ ei, const float* __restrict__ ea){
    int e = blockIdx.x*blockDim.x + threadIdx.x;
    if (e >= NE) return;
    int s = ei[e];
    int d = ei[NE + e];
    int p = g_rowptr[d] + atomicAdd(&g_fill[d], 1);
    g_srcs[p] = s;
    const float* a = ea + e*3;
    g_ea[p] = make_float4(a[0], a[1], a[2], 0.f);
}

__global__ void k_seginit(const int* __restrict__ batch, const float* __restrict__ xm){
    const int nchunk = (NN + gridDim.x - 1) / gridDim.x;
    int n0 = blockIdx.x * nchunk;
    int n1 = min(n0 + nchunk, NN);
    int t = threadIdx.x;
    if (n0 >= n1) return;
    int cur = batch[n0];
    float aG = 0.f, aB = 0.f, cG = 0.f, cB = 0.f;
    for (int n = n0; n < n1; n++){
        int b = batch[n];
        if (b != cur){
            atomicAdd(&g_gsum[cur*HD+t], aG);
            atomicAdd(&g_bcsum[cur*HD+t], aB);
            if (t == 0){ atomicAdd(&g_gcnt[cur], cG); atomicAdd(&g_bccnt[cur], cB); }
            aG = aB = cG = cB = 0.f; cur = b;
        }
        float hv = g_h[n*HD + t];
        float bc = xm[n*3 + 2];
        aG += hv; aB += hv*bc;
        if (t == 0){ cG += 1.f; cB += bc; }
    }
    atomicAdd(&g_gsum[cur*HD+t], aG);
    atomicAdd(&g_bcsum[cur*HD+t], aB);
    if (t == 0){ atomicAdd(&g_gcnt[cur], cG); atomicAdd(&g_bccnt[cur], cB); }
}

__global__ void k_divinit(){
    int i = threadIdx.x;
    int g = i >> 7;
    g_xg[i]  = g_gsum[i]  / fmaxf(g_gcnt[g], 1.f);
    g_xbc[i] = g_bcsum[i] / fmaxf(g_bccnt[g], 1.f);
}

__global__ void k_segzero(){
    int i = threadIdx.x;
    g_gsum[i] = 0.f;
    if (i < NBATCH) g_gcnt[i] = 0.f;
}

__global__ void k_segsum(const int* __restrict__ batch){
    const int nchunk = (NN + gridDim.x - 1) / gridDim.x;
    int n0 = blockIdx.x * nchunk;
    int n1 = min(n0 + nchunk, NN);
    int t = threadIdx.x;
    if (n0 >= n1) return;
    int cur = batch[n0];
    float aG = 0.f, cG = 0.f;
    for (int n = n0; n < n1; n++){
        int b = batch[n];
        if (b != cur){
            atomicAdd(&g_gsum[cur*HD+t], aG);
            if (t == 0) atomicAdd(&g_gcnt[cur], cG);
            aG = 0.f; cG = 0.f; cur = b;
        }
        aG += g_h[n*HD + t];
        if (t == 0) cG += 1.f;
    }
    atomicAdd(&g_gsum[cur*HD+t], aG);
    if (t == 0) atomicAdd(&g_gcnt[cur], cG);
}

__global__ void k_segdiv(){
    int i = threadIdx.x;
    int g = i >> 7;
    g_xg[i] = g_gsum[i] / fmaxf(g_gcnt[g], 1.f);
}

__global__ void k_gb(const float* __restrict__ Wu, const float* __restrict__ bu){
    int g = blockIdx.x, t = threadIdx.x;
    float acc = bu[t];
    #pragma unroll 4
    for (int k = 0; k < 128; k++) acc += g_xg[g*HD+k]  * Wu[(256+k)*128 + t];
    #pragma unroll 4
    for (int k = 0; k < 128; k++) acc += g_xbc[g*HD+k] * Wu[(384+k)*128 + t];
    g_gb[g*HD + t] = acc;
}

// ---------------- GEMM1: P[NP,256] = h[NP,128] @ B1^T  (bf16x3 mma.sync) ------
__global__ void __launch_bounds__(256, 1) k_gemm1(){
    extern __shared__ __nv_bfloat16 sm[];
    int tid = threadIdx.x;
    int w = tid >> 5, l = tid & 31;
    int row0 = blockIdx.x * 128;
    int cchunk = blockIdx.y;          // 0 or 1: output cols cchunk*128

    load_A_tile(g_h + (size_t)row0*128, sm + SM_AHI, sm + SM_ALO, tid);
    load_B_tile(g_B1hi + (size_t)cchunk*128*128, 128, sm + SM_BHI, tid);
    load_B_tile(g_B1lo + (size_t)cchunk*128*128, 128, sm + SM_BLO, tid);
    __syncthreads();

    float acc[2][8][4];
    #pragma unroll
    for (int mb = 0; mb < 2; mb++)
        #pragma unroll
        for (int nb = 0; nb < 8; nb++)
            #pragma unroll
            for (int c = 0; c < 4; c++) acc[mb][nb][c] = 0.f;

    mma_stage(sm, acc, w, l);

    int wm = w >> 1, wn = w & 1;
    int g = l >> 2, t2 = (l & 3) * 2;
    #pragma unroll
    for (int mb = 0; mb < 2; mb++){
        int row = row0 + wm*32 + mb*16 + g;
        #pragma unroll
        for (int nb = 0; nb < 8; nb++){
            int col = cchunk*128 + wn*64 + nb*8 + t2;
            *(float2*)&g_P[(size_t)row*256 + col]       = make_float2(acc[mb][nb][0], acc[mb][nb][1]);
            *(float2*)&g_P[(size_t)(row+8)*256 + col]   = make_float2(acc[mb][nb][2], acc[mb][nb][3]);
        }
    }
}

// ---------------- edge aggregation over CSR (no atomics) ----------------
__global__ void k_agg(const float* __restrict__ Wm, const float* __restrict__ bm){
    int n = blockIdx.x;
    int t = threadIdx.x;
    float base = g_P[n*256 + 128 + t] + bm[t];
    float w0 = Wm[256*128 + t], w1 = Wm[257*128 + t], w2 = Wm[258*128 + t];
    int s0 = g_rowptr[n], s1 = g_rowptr[n+1];
    float acc = 0.f;
    int k = s0;
    for (; k + 1 < s1; k += 2){
        int sA = g_srcs[k], sB = g_srcs[k+1];
        float4 eA = g_ea[k], eB = g_ea[k+1];
        float pA = g_P[sA*256 + t];
        float pB = g_P[sB*256 + t];
        acc += fmaxf(pA + base + eA.x*w0 + eA.y*w1 + eA.z*w2, 0.f);
        acc += fmaxf(pB + base + eB.x*w0 + eB.y*w1 + eB.z*w2, 0.f);
    }
    if (k < s1){
        int s = g_srcs[k];
        float4 e = g_ea[k];
        acc += fmaxf(g_P[s*256 + t] + base + e.x*w0 + e.y*w1 + e.z*w2, 0.f);
    }
    g_agg[n*HD + t] = acc * g_invdeg[n];
}

// ---------------- GEMM2: h += relu([h|agg] @ B2^T + gb[batch]) (bf16x3) -------
__global__ void __launch_bounds__(256, 1) k_gemm2(const int* __restrict__ batch){
    extern __shared__ __nv_bfloat16 sm[];
    int tid = threadIdx.x;
    int w = tid >> 5, l = tid & 31;
    int row0 = blockIdx.x * 128;

    float acc[2][8][4];
    #pragma unroll
    for (int mb = 0; mb < 2; mb++)
        #pragma unroll
        for (int nb = 0; nb < 8; nb++)
            #pragma unroll
            for (int c = 0; c < 4; c++) acc[mb][nb][c] = 0.f;

    for (int kh = 0; kh < 2; kh++){
        if (kh) __syncthreads();      // all warps done with previous stage smem
        const float* A = (kh == 0 ? g_h : g_agg) + (size_t)row0*128;
        load_A_tile(A, sm + SM_AHI, sm + SM_ALO, tid);
        // B rows: [n][ kh*128 + kk ], source pitch 256
        load_B_tile(g_B2hi + kh*128, 256, sm + SM_BHI, tid);
        load_B_tile(g_B2lo + kh*128, 256, sm + SM_BLO, tid);
        __syncthreads();
        mma_stage(sm, acc, w, l);
    }

    int wm = w >> 1, wn = w & 1;
    int g = l >> 2, t2 = (l & 3) * 2;
    #pragma unroll
    for (int mb = 0; mb < 2; mb++){
        int row_a = row0 + wm*32 + mb*16 + g;
        #pragma unroll
        for (int half = 0; half < 2; half++){
            int row = row_a + half*8;
            if (row < NN){
                int b = batch[row];
                #pragma unroll
                for (int nb = 0; nb < 8; nb++){
                    int col = wn*64 + nb*8 + t2;
                    float v0 = acc[mb][nb][half*2+0] + g_gb[b*128 + col];
                    float v1 = acc[mb][nb][half*2+1] + g_gb[b*128 + col + 1];
                    float* hp = g_h + (size_t)row*128 + col;
                    float2 hv = *(float2*)hp;
                    hv.x += fmaxf(v0, 0.f);
                    hv.y += fmaxf(v1, 0.f);
                    *(float2*)hp = hv;
                }
            } else {
                #pragma unroll
                for (int nb = 0; nb < 8; nb++){
                    int col = wn*64 + nb*8 + t2;
                    *(float2*)&g_h[(size_t)row*128 + col] = make_float2(0.f, 0.f);
                }
            }
        }
    }
}

// ---------------- decode + weighted global sums (warp per 32 nodes) ----------
__global__ void k_decode(const float* __restrict__ Wd, const float* __restrict__ bd,
                         float* __restrict__ out){
    int gw = (blockIdx.x*blockDim.x + threadIdx.x) >> 5;
    int l = threadIdx.x & 31;
    int n0 = gw * 32;
    if (n0 >= NN) return;
    int n1 = min(n0 + 32, NN);
    float wd0[4], wd1[4], wd2[4], wd3[4];
    #pragma unroll
    for (int c = 0; c < 4; c++){
        wd0[c] = Wd[(l*4+0)*4 + c];
        wd1[c] = Wd[(l*4+1)*4 + c];
        wd2[c] = Wd[(l*4+2)*4 + c];
        wd3[c] = Wd[(l*4+3)*4 + c];
    }
    float b0 = bd[0], b1 = bd[1], b2 = bd[2], b3 = bd[3];
    float S0=0.f, S1=0.f, S2=0.f, S3=0.f, wacc=0.f;
    for (int n = n0; n < n1; n++){
        float4 hv = *(const float4*)&g_h[(size_t)n*128 + l*4];
        float wn = g_w[n];
        float onew = 1.f + wn;
        S0 += onew*hv.x; S1 += onew*hv.y; S2 += onew*hv.z; S3 += onew*hv.w;
        if (l == 0) wacc += wn;
        float p0 = hv.x*wd0[0] + hv.y*wd1[0] + hv.z*wd2[0] + hv.w*wd3[0];
        float p1 = hv.x*wd0[1] + hv.y*wd1[1] + hv.z*wd2[1] + hv.w*wd3[1];
        float p2 = hv.x*wd0[2] + hv.y*wd1[2] + hv.z*wd2[2] + hv.w*wd3[2];
        float p3 = hv.x*wd0[3] + hv.y*wd1[3] + hv.z*wd2[3] + hv.w*wd3[3];
        #pragma unroll
        for (int off = 16; off > 0; off >>= 1){
            p0 += __shfl_down_sync(0xffffffffu, p0, off);
            p1 += __shfl_down_sync(0xffffffffu, p1, off);
            p2 += __shfl_down_sync(0xffffffffu, p2, off);
            p3 += __shfl_down_sync(0xffffffffu, p3, off);
        }
        if (l == 0)
            *(float4*)&out[(size_t)(1+n)*4] = make_float4(p0+b0, p1+b1, p2+b2, p3+b3);
    }
    atomicAdd(&g_S[l*4+0], S0);
    atomicAdd(&g_S[l*4+1], S1);
    atomicAdd(&g_S[l*4+2], S2);
    atomicAdd(&g_S[l*4+3], S3);
    if (l == 0) atomicAdd(&g_sw, wacc);
}

__global__ void k_final(const float* __restrict__ Wd, const float* __restrict__ bd,
                        float* __restrict__ out){
    __shared__ float sred[4][4];
    int t = threadIdx.x;
    int lane = t & 31, wp = t >> 5;
    float enc = g_S[t] / ((float)NN + g_sw);
    float p0 = enc*Wd[t*4], p1 = enc*Wd[t*4+1], p2 = enc*Wd[t*4+2], p3 = enc*Wd[t*4+3];
    #pragma unroll
    for (int off = 16; off > 0; off >>= 1){
        p0 += __shfl_down_sync(0xffffffffu, p0, off);
        p1 += __shfl_down_sync(0xffffffffu, p1, off);
        p2 += __shfl_down_sync(0xffffffffu, p2, off);
        p3 += __shfl_down_sync(0xffffffffu, p3, off);
    }
    if (lane == 0){ sred[wp][0]=p0; sred[wp][1]=p1; sred[wp][2]=p2; sred[wp][3]=p3; }
    __syncthreads();
    if (t < 4)
        out[t] = sred[0][t] + sred[1][t] + sred[2][t] + sred[3][t] + bd[t];
}

// ---------------- launch ----------------
extern "C" void kernel_launch(void* const* d_in, const int* in_sizes, int n_in,
                              void* d_out, int out_size){
    (void)in_sizes; (void)n_in; (void)out_size;
    const float* x   = (const float*)d_in[0];
    const float* xm  = (const float*)d_in[1];
    const int*   ei  = (const int*)  d_in[2];
    const float* ea  = (const float*)d_in[3];
    const float* pos = (const float*)d_in[4];
    const int*   bat = (const int*)  d_in[5];
    const float* sp  = (const float*)d_in[6];
    const float* M   = (const float*)d_in[7];
    const float* We  = (const float*)d_in[8];
    const float* be  = (const float*)d_in[9];
    const float* Wm  = (const float*)d_in[10];
    const float* bm  = (const float*)d_in[11];
    const float* Wu  = (const float*)d_in[12];
    const float* bu  = (const float*)d_in[13];
    const float* Wd  = (const float*)d_in[14];
    const float* bd  = (const float*)d_in[15];
    float* out = (float*)d_out;

    static int attr_done = 0;
    if (!attr_done){
        cudaFuncSetAttribute(k_gemm1, cudaFuncAttributeMaxDynamicSharedMemorySize, SM_TOTAL_BYTES);
        cudaFuncSetAttribute(k_gemm2, cudaFuncAttributeMaxDynamicSharedMemorySize, SM_TOTAL_BYTES);
        attr_done = 1;
    }

    k_zero   <<<(NN+255)/256, 256>>>();
    k_packB1 <<<128, 256>>>(Wm);
    k_packB2 <<<128, 256>>>(Wu);
    k_encode <<<(NN+1)/2, 256>>>(x, xm, We, be);
    k_wcoef  <<<(NN+255)/256, 256>>>(pos, M, sp);
    k_count  <<<(NE+255)/256, 256>>>(ei);
    k_scan   <<<1, 1024>>>();
    k_scatter<<<(NE+255)/256, 256>>>(ei, ea);
    k_seginit<<<512, 128>>>(bat, xm);
    k_divinit<<<1, 1024>>>();

    for (int r = 0; r < 4; r++){
        dim3 g1(NBLK, 2);
        k_gemm1<<<g1, 256, SM_TOTAL_BYTES>>>();
        k_agg  <<<NN, 128>>>(Wm, bm);
        k_gb   <<<NBATCH, 128>>>(Wu, bu);
        k_gemm2<<<NBLK, 256, SM_TOTAL_BYTES>>>(bat);
        if (r < 3){
            k_segzero<<<1, 1024>>>();
            k_segsum <<<512, 128>>>(bat);
            k_segdiv <<<1, 1024>>>();
        }
    }

    k_decode<<<196, 256>>>(Wd, bd, out);
    k_final <<<1, 128>>>(Wd, bd, out);
}

// round 4
// speedup vs baseline: 1.5560x; 1.1245x over previous
#include <cuda_runtime.h>
#include <cuda_bf16.h>
#include <cstdint>

#define NN 50000
#define NE 800000
#define NBATCH 8
#define HD 128
#define NBLK 391
#define NP (NBLK*128)   // 50048 padded rows
#define SCAN_NB 196

// ---------------- device scratch (static, no allocations) ----------------
__device__ float  g_h[NP*HD];
__device__ float  g_Psrc[NP*HD];
__device__ float  g_Pdst[NP*HD];
__device__ float  g_agg[NP*HD];
__device__ int    g_cnt[NN];
__device__ int    g_fill[NN];
__device__ int    g_rowptr[NN+1];
__device__ int    g_bsum[SCAN_NB];
__device__ int    g_srcs[NE];
__device__ float4 g_ea[NE];
__device__ float  g_invdeg[NN];
__device__ float  g_w[NN];
__device__ float  g_gsum[NBATCH*HD];
__device__ float  g_gcnt[NBATCH];
__device__ float  g_bcsum[NBATCH*HD];
__device__ float  g_bccnt[NBATCH];
__device__ float  g_gbc[NBATCH*HD];   // b_upd + xBC @ Wu[384:512]  (constant over repeats)
__device__ float  g_gb[NBATCH*HD];
__device__ float  g_S[HD];
__device__ float  g_sw;
// pre-split bf16 weights, [N][K] row-major (K contiguous)
__device__ __nv_bfloat16 g_B1hi[256*128];
__device__ __nv_bfloat16 g_B1lo[256*128];
__device__ __nv_bfloat16 g_B2hi[128*256];
__device__ __nv_bfloat16 g_B2lo[128*256];

// ---------------- smem geometry ----------------
#define PITCH 136                     // bf16 elements per row (272B, conflict-free)
#define TILE_ELEMS (128*PITCH)        // 17408 bf16 per tile
#define SM_AHI 0
#define SM_ALO (TILE_ELEMS)
#define SM_BHI (2*TILE_ELEMS)
#define SM_BLO (3*TILE_ELEMS)
#define SM_TOTAL_BYTES (4*TILE_ELEMS*2)   // 139264

// ---------------- mma / ldmatrix helpers ----------------
__device__ __forceinline__ void mma16816(float* d, const uint32_t* a, const uint32_t* b){
    asm volatile("mma.sync.aligned.m16n8k16.row.col.f32.bf16.bf16.f32 "
        "{%0,%1,%2,%3}, {%4,%5,%6,%7}, {%8,%9}, {%0,%1,%2,%3};"
        : "+f"(d[0]), "+f"(d[1]), "+f"(d[2]), "+f"(d[3])
        : "r"(a[0]), "r"(a[1]), "r"(a[2]), "r"(a[3]), "r"(b[0]), "r"(b[1]));
}
__device__ __forceinline__ void ldsm4(uint32_t& r0, uint32_t& r1, uint32_t& r2, uint32_t& r3,
                                      uint32_t addr){
    asm volatile("ldmatrix.sync.aligned.m8n8.x4.shared.b16 {%0,%1,%2,%3}, [%4];"
        : "=r"(r0), "=r"(r1), "=r"(r2), "=r"(r3) : "r"(addr));
}
// pack two floats (lo elem, hi elem) as bf16x2 word (memory order lo,hi)
__device__ __forceinline__ uint32_t bf2(float lo, float hi){
    uint32_t r; asm("cvt.rn.bf16x2.f32 %0, %1, %2;" : "=r"(r) : "f"(hi), "f"(lo));
    return r;
}
__device__ __forceinline__ void bsplit(float v, __nv_bfloat16& hi, __nv_bfloat16& lo){
    hi = __float2bfloat16(v);
    lo = __float2bfloat16(v - __bfloat162float(hi));
}

// load 128x128 float A block -> smem hi/lo bf16 tiles (pitch PITCH)
__device__ __forceinline__ void load_A_tile(const float* A, __nv_bfloat16* sAhi,
                                            __nv_bfloat16* sAlo, int tid){
    const float4* A4 = (const float4*)A;
    #pragma unroll
    for (int i = 0; i < 16; i++){
        int f = tid + i*256;
        int r = f >> 5, c4 = f & 31;
        float4 v = A4[f];
        float h0 = __bfloat162float(__float2bfloat16(v.x));
        float h1 = __bfloat162float(__float2bfloat16(v.y));
        float h2 = __bfloat162float(__float2bfloat16(v.z));
        float h3 = __bfloat162float(__float2bfloat16(v.w));
        uint2 hp = make_uint2(bf2(h0, h1), bf2(h2, h3));
        uint2 lp = make_uint2(bf2(v.x - h0, v.y - h1), bf2(v.z - h2, v.w - h3));
        *(uint2*)(sAhi + r*PITCH + c4*4) = hp;
        *(uint2*)(sAlo + r*PITCH + c4*4) = lp;
    }
}

// copy 128x128 bf16 block (row stride srcPitch) -> smem (pitch PITCH)
__device__ __forceinline__ void load_B_tile(const __nv_bfloat16* src, int srcPitch,
                                            __nv_bfloat16* dst, int tid){
    #pragma unroll
    for (int i = 0; i < 8; i++){
        int f = tid + i*256;
        int n = f >> 4, k8 = f & 15;
        *(uint4*)(dst + n*PITCH + k8*8) = *(const uint4*)(src + n*srcPitch + k8*8);
    }
}

// one K=128 compute stage: acc += Ahi*Bhi + Alo*Bhi + Ahi*Blo   (ldmatrix loads)
__device__ __forceinline__ void mma_stage(uint32_t sb, float acc[2][8][4], int w, int l){
    const uint32_t AHI = SM_AHI*2, ALO = SM_ALO*2, BHI = SM_BHI*2, BLO = SM_BLO*2;
    int wm = w >> 1, wn = w & 1;
    uint32_t acol = (l & 16) ? 16u : 0u;                 // +8 elems in bytes
    uint32_t aoff0 = (uint32_t)((wm*32 + (l & 15))*PITCH)*2 + acol;
    uint32_t aoff1 = aoff0 + 16*PITCH*2;
    uint32_t bcol = (l & 8) ? 16u : 0u;
    uint32_t boff = (uint32_t)((wn*64 + (l & 7) + ((l & 16) ? 8 : 0))*PITCH)*2 + bcol;
    #pragma unroll
    for (int ks = 0; ks < 8; ks++){
        uint32_t ko = (uint32_t)ks*32;                   // 16 bf16 in bytes
        uint32_t ah[2][4], al[2][4], bh[8][2], bl[8][2];
        ldsm4(ah[0][0], ah[0][1], ah[0][2], ah[0][3], sb + AHI + aoff0 + ko);
        ldsm4(ah[1][0], ah[1][1], ah[1][2], ah[1][3], sb + AHI + aoff1 + ko);
        ldsm4(al[0][0], al[0][1], al[0][2], al[0][3], sb + ALO + aoff0 + ko);
        ldsm4(al[1][0], al[1][1], al[1][2], al[1][3], sb + ALO + aoff1 + ko);
        #pragma unroll
        for (int nb2 = 0; nb2 < 4; nb2++){
            uint32_t bo = boff + (uint32_t)(nb2*16*PITCH)*2 + ko;
            ldsm4(bh[2*nb2][0], bh[2*nb2][1], bh[2*nb2+1][0], bh[2*nb2+1][1], sb + BHI + bo);
            ldsm4(bl[2*nb2][0], bl[2*nb2][1], bl[2*nb2+1][0], bl[2*nb2+1][1], sb + BLO + bo);
        }
        #pragma unroll
        for (int mb = 0; mb < 2; mb++)
            #pragma unroll
            for (int nb = 0; nb < 8; nb++){
                mma16816(acc[mb][nb], ah[mb], bh[nb]);
                mma16816(acc[mb][nb], al[mb], bh[nb]);
                mma16816(acc[mb][nb], ah[mb], bl[nb]);
            }
    }
}

// ---------------- setup kernels ----------------
__global__ void k_zero(){
    int i = blockIdx.x*blockDim.x + threadIdx.x;
    if (i < NN){ g_cnt[i] = 0; g_fill[i] = 0; }
    if (i < NBATCH*HD){ g_gsum[i] = 0.f; g_bcsum[i] = 0.f; }
    if (i < NBATCH){ g_gcnt[i] = 0.f; g_bccnt[i] = 0.f; }
    if (i < HD) g_S[i] = 0.f;
    if (i == 0) g_sw = 0.f;
}

__global__ void k_packB1(const float* __restrict__ Wm){
    int i = blockIdx.x*blockDim.x + threadIdx.x;
    if (i >= 256*128) return;
    int n = i >> 7, k = i & 127;
    float v = (n < 128) ? Wm[k*128 + n] : Wm[(128+k)*128 + (n-128)];
    __nv_bfloat16 hi, lo; bsplit(v, hi, lo);
    g_B1hi[i] = hi; g_B1lo[i] = lo;
}

__global__ void k_packB2(const float* __restrict__ Wu){
    int i = blockIdx.x*blockDim.x + threadIdx.x;
    if (i >= 128*256) return;
    int n = i >> 8, k = i & 255;
    float v = Wu[k*128 + n];
    __nv_bfloat16 hi, lo; bsplit(v, hi, lo);
    g_B2hi[i] = hi; g_B2lo[i] = lo;
}

// h0 = relu([x|x_mask] @ W_enc + b_enc)  — 32 threads per node, float4 cols
__global__ void k_encode(const float* __restrict__ x, const float* __restrict__ xm,
                         const float* __restrict__ We, const float* __restrict__ be){
    int node = blockIdx.x*8 + (threadIdx.x >> 5);
    int c = threadIdx.x & 31;
    if (node >= NN) return;
    const float4* We4 = (const float4*)We;
    float4 acc = ((const float4*)be)[c];
    const float* xr = x  + node*5;
    const float* mr = xm + node*3;
    float in[8] = {xr[0], xr[1], xr[2], xr[3], xr[4], mr[0], mr[1], mr[2]};
    #pragma unroll
    for (int j = 0; j < 8; j++){
        float4 wv = We4[j*32 + c];
        acc.x += in[j]*wv.x; acc.y += in[j]*wv.y;
        acc.z += in[j]*wv.z; acc.w += in[j]*wv.w;
    }
    acc.x = fmaxf(acc.x, 0.f); acc.y = fmaxf(acc.y, 0.f);
    acc.z = fmaxf(acc.z, 0.f); acc.w = fmaxf(acc.w, 0.f);
    *(float4*)&g_h[(size_t)node*HD + c*4] = acc;
}

__global__ void k_wcoef(const float* __restrict__ pos, const float* __restrict__ M,
                        const float* __restrict__ sp){
    int i = blockIdx.x*blockDim.x + threadIdx.x;
    if (i >= NN) return;
    float d0 = pos[i*2]   - sp[0];
    float d1 = pos[i*2+1] - sp[1];
    float sum = 0.f;
    #pragma unroll 8
    for (int j = 0; j < 64; j++)
        sum += __cosf(d0*M[j] + d1*M[64+j]);
    g_w[i] = sum * (1.f/64.f);
}

__global__ void k_count(const int* __restrict__ ei){
    int e = blockIdx.x*blockDim.x + threadIdx.x;
    if (e < NE) atomicAdd(&g_cnt[ei[NE + e]], 1);
}

// ---- 3-phase parallel scan of degree counts -> rowptr ----
__global__ void k_scan1(){
    int b = blockIdx.x, t = threadIdx.x;
    int n = b*256 + t;
    int v = (n < NN) ? g_cnt[n] : 0;
    if (n < NN) g_invdeg[n] = 1.f / (float)max(v, 1);
    int lane = t & 31, wp = t >> 5;
    int x = v;
    #pragma unroll
    for (int off = 1; off < 32; off <<= 1){
        int y = __shfl_up_sync(0xffffffffu, x, off);
        if (lane >= off) x += y;
    }
    __shared__ int ws[8];
    if (lane == 31) ws[wp] = x;
    __syncthreads();
    if (t == 0){
        int run = 0;
        #pragma unroll
        for (int i = 0; i < 8; i++){ int tmp = ws[i]; ws[i] = run; run += tmp; }
        g_bsum[b] = run;
    }
    __syncthreads();
    if (n < NN) g_rowptr[n] = x - v + ws[wp];
}

__global__ void k_scan2(){
    int t = threadIdx.x;
    int v = (t < SCAN_NB) ? g_bsum[t] : 0;
    int lane = t & 31, wp = t >> 5;
    int x = v;
    #pragma unroll
    for (int off = 1; off < 32; off <<= 1){
        int y = __shfl_up_sync(0xffffffffu, x, off);
        if (lane >= off) x += y;
    }
    __shared__ int ws[8];
    if (lane == 31) ws[wp] = x;
    __syncthreads();
    if (t == 0){
        int run = 0;
        #pragma unroll
        for (int i = 0; i < 8; i++){ int tmp = ws[i]; ws[i] = run; run += tmp; }
        g_rowptr[NN] = run;
    }
    __syncthreads();
    if (t < SCAN_NB) g_bsum[t] = x - v + ws[wp];
}

__global__ void k_scan3(){
    int n = blockIdx.x*256 + threadIdx.x;
    if (n < NN) g_rowptr[n] += g_bsum[n >> 8];
}

__global__ void k_scatter(const int* __restrict__ ei, const float* __restrict__ ea){
    int e = blockIdx.x*blockDim.x + threadIdx.x;
    if (e >= NE) return;
    int s = ei[e];
    int d = ei[NE + e];
    int p = g_rowptr[d] + atomicAdd(&g_fill[d], 1);
    g_srcs[p] = s;
    const float* a = ea + e*3;
    g_ea[p] = make_float4(a[0], a[1], a[2], 0.f);
}

__global__ void k_seginit(const int* __restrict__ batch, const float* __restrict__ xm){
    const int nchunk = (NN + gridDim.x - 1) / gridDim.x;
    int n0 = blockIdx.x * nchunk;
    int n1 = min(n0 + nchunk, NN);
    int t = threadIdx.x;
    if (n0 >= n1) return;
    int cur = batch[n0];
    float aG = 0.f, aB = 0.f, cG = 0.f, cB = 0.f;
    for (int n = n0; n < n1; n++){
        int b = batch[n];
        if (b != cur){
            atomicAdd(&g_gsum[cur*HD+t], aG);
            atomicAdd(&g_bcsum[cur*HD+t], aB);
            if (t == 0){ atomicAdd(&g_gcnt[cur], cG); atomicAdd(&g_bccnt[cur], cB); }
            aG = aB = cG = cB = 0.f; cur = b;
        }
        float hv = g_h[n*HD + t];
        float bc = xm[n*3 + 2];
        aG += hv; aB += hv*bc;
        if (t == 0){ cG += 1.f; cB += bc; }
    }
    atomicAdd(&g_gsum[cur*HD+t], aG);
    atomicAdd(&g_bcsum[cur*HD+t], aB);
    if (t == 0){ atomicAdd(&g_gcnt[cur], cG); atomicAdd(&g_bccnt[cur], cB); }
}

// gbc = b_upd + xBC @ Wu[384:512]   (constant over repeats)
__global__ void k_initgbc(const float* __restrict__ Wu, const float* __restrict__ bu){
    int g = blockIdx.x, t = threadIdx.x;
    __shared__ float sx[128];
    float bcc = fmaxf(g_bccnt[g], 1.f);
    sx[t] = g_bcsum[g*HD + t] / bcc;
    __syncthreads();
    float acc = bu[t];
    #pragma unroll 4
    for (int k = 0; k < 128; k++) acc += sx[k] * Wu[(384+k)*128 + t];
    g_gbc[g*HD + t] = acc;
}

// gb = gbc + xg @ Wu[256:384]; also finishes seg-mean and re-zeros the sums
__global__ void k_prep(const float* __restrict__ Wu){
    int g = blockIdx.x, t = threadIdx.x;
    __shared__ float sx[128];
    float c = fmaxf(g_gcnt[g], 1.f);
    sx[t] = g_gsum[g*HD + t] / c;
    __syncthreads();
    float acc = g_gbc[g*HD + t];
    #pragma unroll 4
    for (int k = 0; k < 128; k++) acc += sx[k] * Wu[(256+k)*128 + t];
    g_gb[g*HD + t] = acc;
    g_gsum[g*HD + t] = 0.f;
    if (t == 0) g_gcnt[g] = 0.f;
}

__global__ void k_segsum(const int* __restrict__ batch){
    const int nchunk = (NN + gridDim.x - 1) / gridDim.x;
    int n0 = blockIdx.x * nchunk;
    int n1 = min(n0 + nchunk, NN);
    int t = threadIdx.x;
    if (n0 >= n1) return;
    int cur = batch[n0];
    float aG = 0.f, cG = 0.f;
    for (int n = n0; n < n1; n++){
        int b = batch[n];
        if (b != cur){
            atomicAdd(&g_gsum[cur*HD+t], aG);
            if (t == 0) atomicAdd(&g_gcnt[cur], cG);
            aG = 0.f; cG = 0.f; cur = b;
        }
        aG += g_h[n*HD + t];
        if (t == 0) cG += 1.f;
    }
    atomicAdd(&g_gsum[cur*HD+t], aG);
    if (t == 0) atomicAdd(&g_gcnt[cur], cG);
}

// ---------------- GEMM1: Psrc/Pdst = h @ B1^T  (bf16x3 mma + ldmatrix) --------
__global__ void __launch_bounds__(256, 1) k_gemm1(const float* __restrict__ bm){
    extern __shared__ __nv_bfloat16 sm[];
    uint32_t sb = (uint32_t)__cvta_generic_to_shared(sm);
    int tid = threadIdx.x;
    int w = tid >> 5, l = tid & 31;
    int row0 = blockIdx.x * 128;
    int cchunk = blockIdx.y;          // 0 -> Psrc cols, 1 -> Pdst cols

    load_A_tile(g_h + (size_t)row0*128, sm + SM_AHI, sm + SM_ALO, tid);
    load_B_tile(g_B1hi + (size_t)cchunk*128*128, 128, sm + SM_BHI, tid);
    load_B_tile(g_B1lo + (size_t)cchunk*128*128, 128, sm + SM_BLO, tid);
    __syncthreads();

    float acc[2][8][4];
    #pragma unroll
    for (int mb = 0; mb < 2; mb++)
        #pragma unroll
        for (int nb = 0; nb < 8; nb++)
            #pragma unroll
            for (int c = 0; c < 4; c++) acc[mb][nb][c] = 0.f;

    mma_stage(sb, acc, w, l);

    float* dstbuf = cchunk ? g_Pdst : g_Psrc;
    int wm = w >> 1, wn = w & 1;
    int g = l >> 2, t2 = (l & 3) * 2;
    #pragma unroll
    for (int mb = 0; mb < 2; mb++){
        int row = row0 + wm*32 + mb*16 + g;
        #pragma unroll
        for (int nb = 0; nb < 8; nb++){
            int col = wn*64 + nb*8 + t2;
            float bias0 = cchunk ? bm[col]   : 0.f;
            float bias1 = cchunk ? bm[col+1] : 0.f;
            *(float2*)&dstbuf[(size_t)row*128 + col] =
                make_float2(acc[mb][nb][0] + bias0, acc[mb][nb][1] + bias1);
            *(float2*)&dstbuf[(size_t)(row+8)*128 + col] =
                make_float2(acc[mb][nb][2] + bias0, acc[mb][nb][3] + bias1);
        }
    }
}

// ---------------- edge aggregation over CSR (no atomics) ----------------
__global__ void k_agg(const float* __restrict__ Wm){
    int n = blockIdx.x;
    int t = threadIdx.x;
    float base = g_Pdst[(size_t)n*128 + t];   // includes b_msg
    float w0 = Wm[256*128 + t], w1 = Wm[257*128 + t], w2 = Wm[258*128 + t];
    int s0 = g_rowptr[n], s1 = g_rowptr[n+1];
    float acc = 0.f;
    int k = s0;
    for (; k + 1 < s1; k += 2){
        int sA = g_srcs[k], sB = g_srcs[k+1];
        float4 eA = g_ea[k], eB = g_ea[k+1];
        float pA = g_Psrc[(size_t)sA*128 + t];
        float pB = g_Psrc[(size_t)sB*128 + t];
        acc += fmaxf(pA + base + eA.x*w0 + eA.y*w1 + eA.z*w2, 0.f);
        acc += fmaxf(pB + base + eB.x*w0 + eB.y*w1 + eB.z*w2, 0.f);
    }
    if (k < s1){
        int s = g_srcs[k];
        float4 e = g_ea[k];
        acc += fmaxf(g_Psrc[(size_t)s*128 + t] + base + e.x*w0 + e.y*w1 + e.z*w2, 0.f);
    }
    g_agg[(size_t)n*HD + t] = acc * g_invdeg[n];
}

// ---------------- GEMM2: h += relu([h|agg] @ B2^T + gb[batch]) ----------------
__global__ void __launch_bounds__(256, 1) k_gemm2(const int* __restrict__ batch){
    extern __shared__ __nv_bfloat16 sm[];
    uint32_t sb = (uint32_t)__cvta_generic_to_shared(sm);
    int tid = threadIdx.x;
    int w = tid >> 5, l = tid & 31;
    int row0 = blockIdx.x * 128;

    float acc[2][8][4];
    #pragma unroll
    for (int mb = 0; mb < 2; mb++)
        #pragma unroll
        for (int nb = 0; nb < 8; nb++)
            #pragma unroll
            for (int c = 0; c < 4; c++) acc[mb][nb][c] = 0.f;

    for (int kh = 0; kh < 2; kh++){
        if (kh) __syncthreads();
        const float* A = (kh == 0 ? g_h : g_agg) + (size_t)row0*128;
        load_A_tile(A, sm + SM_AHI, sm + SM_ALO, tid);
        load_B_tile(g_B2hi + kh*128, 256, sm + SM_BHI, tid);
        load_B_tile(g_B2lo + kh*128, 256, sm + SM_BLO, tid);
        __syncthreads();
        mma_stage(sb, acc, w, l);
    }

    int wm = w >> 1, wn = w & 1;
    int g = l >> 2, t2 = (l & 3) * 2;
    #pragma unroll
    for (int mb = 0; mb < 2; mb++){
        int row_a = row0 + wm*32 + mb*16 + g;
        #pragma unroll
        for (int half = 0; half < 2; half++){
            int row = row_a + half*8;
            if (row < NN){
                int b = batch[row];
                #pragma unroll
                for (int nb = 0; nb < 8; nb++){
                    int col = wn*64 + nb*8 + t2;
                    float v0 = acc[mb][nb][half*2+0] + g_gb[b*128 + col];
                    float v1 = acc[mb][nb][half*2+1] + g_gb[b*128 + col + 1];
                    float* hp = g_h + (size_t)row*128 + col;
                    float2 hv = *(float2*)hp;
                    hv.x += fmaxf(v0, 0.f);
                    hv.y += fmaxf(v1, 0.f);
                    *(float2*)hp = hv;
                }
            } else {
                #pragma unroll
                for (int nb = 0; nb < 8; nb++){
                    int col = wn*64 + nb*8 + t2;
                    *(float2*)&g_h[(size_t)row*128 + col] = make_float2(0.f, 0.f);
                }
            }
        }
    }
}

// ---------------- decode + weighted global sums (warp per 32 nodes) ----------
__global__ void k_decode(const float* __restrict__ Wd, const float* __restrict__ bd,
                         float* __restrict__ out){
    int gw = (blockIdx.x*blockDim.x + threadIdx.x) >> 5;
    int l = threadIdx.x & 31;
    int n0 = gw * 32;
    if (n0 >= NN) return;
    int n1 = min(n0 + 32, NN);
    float wd0[4], wd1[4], wd2[4], wd3[4];
    #pragma unroll
    for (int c = 0; c < 4; c++){
        wd0[c] = Wd[(l*4+0)*4 + c];
        wd1[c] = Wd[(l*4+1)*4 + c];
        wd2[c] = Wd[(l*4+2)*4 + c];
        wd3[c] = Wd[(l*4+3)*4 + c];
    }
    float b0 = bd[0], b1 = bd[1], b2 = bd[2], b3 = bd[3];
    float S0=0.f, S1=0.f, S2=0.f, S3=0.f, wacc=0.f;
    for (int n = n0; n < n1; n++){
        float4 hv = *(const float4*)&g_h[(size_t)n*128 + l*4];
        float wn = g_w[n];
        float onew = 1.f + wn;
        S0 += onew*hv.x; S1 += onew*hv.y; S2 += onew*hv.z; S3 += onew*hv.w;
        if (l == 0) wacc += wn;
        float p0 = hv.x*wd0[0] + hv.y*wd1[0] + hv.z*wd2[0] + hv.w*wd3[0];
        float p1 = hv.x*wd0[1] + hv.y*wd1[1] + hv.z*wd2[1] + hv.w*wd3[1];
        float p2 = hv.x*wd0[2] + hv.y*wd1[2] + hv.z*wd2[2] + hv.w*wd3[2];
        float p3 = hv.x*wd0[3] + hv.y*wd1[3] + hv.z*wd2[3] + hv.w*wd3[3];
        #pragma unroll
        for (int off = 16; off > 0; off >>= 1){
            p0 += __shfl_down_sync(0xffffffffu, p0, off);
            p1 += __shfl_down_sync(0xffffffffu, p1, off);
            p2 += __shfl_down_sync(0xffffffffu, p2, off);
            p3 += __shfl_down_sync(0xffffffffu, p3, off);
        }
        if (l == 0)
            *(float4*)&out[(size_t)(1+n)*4] = make_float4(p0+b0, p1+b1, p2+b2, p3+b3);
    }
    atomicAdd(&g_S[l*4+0], S0);
    atomicAdd(&g_S[l*4+1], S1);
    atomicAdd(&g_S[l*4+2], S2);
    atomicAdd(&g_S[l*4+3], S3);
    if (l == 0) atomicAdd(&g_sw, wacc);
}

__global__ void k_final(const float* __restrict__ Wd, const float* __restrict__ bd,
                        float* __restrict__ out){
    __shared__ float sred[4][4];
    int t = threadIdx.x;
    int lane = t & 31, wp = t >> 5;
    float enc = g_S[t] / ((float)NN + g_sw);
    float p0 = enc*Wd[t*4], p1 = enc*Wd[t*4+1], p2 = enc*Wd[t*4+2], p3 = enc*Wd[t*4+3];
    #pragma unroll
    for (int off = 16; off > 0; off >>= 1){
        p0 += __shfl_down_sync(0xffffffffu, p0, off);
        p1 += __shfl_down_sync(0xffffffffu, p1, off);
        p2 += __shfl_down_sync(0xffffffffu, p2, off);
        p3 += __shfl_down_sync(0xffffffffu, p3, off);
    }
    if (lane == 0){ sred[wp][0]=p0; sred[wp][1]=p1; sred[wp][2]=p2; sred[wp][3]=p3; }
    __syncthreads();
    if (t < 4)
        out[t] = sred[0][t] + sred[1][t] + sred[2][t] + sred[3][t] + bd[t];
}

// ---------------- launch ----------------
extern "C" void kernel_launch(void* const* d_in, const int* in_sizes, int n_in,
                              void* d_out, int out_size){
    (void)in_sizes; (void)n_in; (void)out_size;
    const float* x   = (const float*)d_in[0];
    const float* xm  = (const float*)d_in[1];
    const int*   ei  = (const int*)  d_in[2];
    const float* ea  = (const float*)d_in[3];
    const float* pos = (const float*)d_in[4];
    const int*   bat = (const int*)  d_in[5];
    const float* sp  = (const float*)d_in[6];
    const float* M   = (const float*)d_in[7];
    const float* We  = (const float*)d_in[8];
    const float* be  = (const float*)d_in[9];
    const float* Wm  = (const float*)d_in[10];
    const float* bm  = (const float*)d_in[11];
    const float* Wu  = (const float*)d_in[12];
    const float* bu  = (const float*)d_in[13];
    const float* Wd  = (const float*)d_in[14];
    const float* bd  = (const float*)d_in[15];
    float* out = (float*)d_out;

    static int attr_done = 0;
    if (!attr_done){
        cudaFuncSetAttribute(k_gemm1, cudaFuncAttributeMaxDynamicSharedMemorySize, SM_TOTAL_BYTES);
        cudaFuncSetAttribute(k_gemm2, cudaFuncAttributeMaxDynamicSharedMemorySize, SM_TOTAL_BYTES);
        attr_done = 1;
    }

    k_zero   <<<(NN+255)/256, 256>>>();
    k_packB1 <<<128, 256>>>(Wm);
    k_packB2 <<<128, 256>>>(Wu);
    k_encode <<<(NN+7)/8, 256>>>(x, xm, We, be);
    k_wcoef  <<<(NN+255)/256, 256>>>(pos, M, sp);
    k_count  <<<(NE+255)/256, 256>>>(ei);
    k_scan1  <<<SCAN_NB, 256>>>();
    k_scan2  <<<1, 256>>>();
    k_scan3  <<<SCAN_NB, 256>>>();
    k_scatter<<<(NE+255)/256, 256>>>(ei, ea);
    k_seginit<<<512, 128>>>(bat, xm);
    k_initgbc<<<NBATCH, 128>>>(Wu, bu);
    k_prep   <<<NBATCH, 128>>>(Wu);

    for (int r = 0; r < 4; r++){
        dim3 g1(NBLK, 2);
        k_gemm1<<<g1, 256, SM_TOTAL_BYTES>>>(bm);
        k_agg  <<<NN, 128>>>(Wm);
        k_gemm2<<<NBLK, 256, SM_TOTAL_BYTES>>>(bat);
        if (r < 3){
            k_segsum<<<512, 128>>>(bat);
            k_prep  <<<NBATCH, 128>>>(Wu);
        }
    }

    k_decode<<<196, 256>>>(Wd, bd, out);
    k_final <<<1, 128>>>(Wd, bd, out);
}